// round 13
// baseline (speedup 1.0000x reference)
#include <cuda_runtime.h>
#include <cuda_bf16.h>
#include <cstdint>

#define NROWS 8191
#define C2    0.011271055006945017f    /* 2*gamma*log2(e), gamma=1/256 */
#define NGL2  0.0056355275034725085f   /* gamma*log2(e) */

// ---------------- device scratch (no allocation allowed) ----------------
__device__ __nv_bfloat16 g_ytb[8192 * 128]; // bf16 yt keys, k-permuted (p16 within 16-blocks)
__device__ float g_vt[128 * 8192];   // tf32 V transposed [dim][key], keys permuted within 8
__device__ float g_cq[8192];         // -gamma*log2e*||bf16(x_i)||^2
__device__ float g_ck[8192];         // -gamma*log2e*||bf16(yt_j)||^2 ; row 8191 -> -1e30

// GEMM2 (tf32 k8) permutation: (k,k+4) adjacent within 8-blocks
__device__ __host__ __forceinline__ int sperm(int k) { return ((k & 3) << 1) | (k >> 2); }
// GEMM1 (bf16 k16) permutation: quad (2t,2t+1,2t+8,2t+9) contiguous within 16-blocks
__device__ __host__ __forceinline__ int p16(int k) {
    return 4 * ((k & 7) >> 1) + (k & 1) + 2 * (k >> 3);
}

// ---------------- helpers ----------------
__device__ __forceinline__ float tf32r(float x) {
    uint32_t u; asm("cvt.rna.tf32.f32 %0, %1;" : "=r"(u) : "f"(x));
    return __uint_as_float(u);
}
__device__ __forceinline__ float ex2f(float x) {
    float r; asm("ex2.approx.f32 %0, %1;" : "=f"(r) : "f"(x)); return r;
}
__device__ __forceinline__ uint32_t smaddr(const void* p) {
    uint32_t a;
    asm("{ .reg .u64 t; cvta.to.shared.u64 t, %1; cvt.u32.u64 %0, t; }" : "=r"(a) : "l"(p));
    return a;
}
#define CP16(dst, src) \
    asm volatile("cp.async.cg.shared.global [%0], [%1], 16;" \
                 :: "r"(dst), "l"((size_t)__cvta_generic_to_global(src)) : "memory")
#define CP_COMMIT() asm volatile("cp.async.commit_group;" ::: "memory")
#define CP_WAIT2()  asm volatile("cp.async.wait_group 2;" ::: "memory")

__device__ __forceinline__ void mma8(float* c, uint32_t a0, uint32_t a1, uint32_t a2,
                                     uint32_t a3, uint32_t b0, uint32_t b1) {
    asm volatile("mma.sync.aligned.m16n8k8.row.col.f32.tf32.tf32.f32 "
                 "{%0,%1,%2,%3}, {%4,%5,%6,%7}, {%8,%9}, {%0,%1,%2,%3};"
                 : "+f"(c[0]), "+f"(c[1]), "+f"(c[2]), "+f"(c[3])
                 : "r"(a0), "r"(a1), "r"(a2), "r"(a3), "r"(b0), "r"(b1));
}
__device__ __forceinline__ void mma16(float* c, uint32_t a0, uint32_t a1, uint32_t a2,
                                      uint32_t a3, uint32_t b0, uint32_t b1) {
    asm volatile("mma.sync.aligned.m16n8k16.row.col.f32.bf16.bf16.f32 "
                 "{%0,%1,%2,%3}, {%4,%5,%6,%7}, {%8,%9}, {%0,%1,%2,%3};"
                 : "+f"(c[0]), "+f"(c[1]), "+f"(c[2]), "+f"(c[3])
                 : "r"(a0), "r"(a1), "r"(a2), "r"(a3), "r"(b0), "r"(b1));
}

// ---------------- kernel 1: yt = y @ R^T + t  -> bf16, p16-permuted --------
__global__ __launch_bounds__(256) void yt_kernel(const float* __restrict__ y,
                                                 const float* __restrict__ R,
                                                 const float* __restrict__ t)
{
    extern __shared__ char smem[];
    float* yT = (float*)smem;                 // [k][row] stride 68
    float* RT = (float*)(smem + 34816);       // [k][c]   stride 132
    const int tid = threadIdx.x;
    const int r0  = blockIdx.x * 64;

    #pragma unroll
    for (int s = 0; s < 32; s++) {
        int e = tid + s * 256, row = e >> 7, k = e & 127, gr = r0 + row;
        yT[k * 68 + row] = (gr < NROWS) ? y[gr * 128 + k] : 0.0f;
    }
    #pragma unroll
    for (int s = 0; s < 64; s++) {
        int e = tid + s * 256, c = e >> 7, k = e & 127;
        RT[k * 132 + c] = R[e];
    }
    __syncthreads();

    const int tr = tid >> 4, tc = tid & 15;
    float acc[4][8];
    #pragma unroll
    for (int i = 0; i < 4; i++)
        #pragma unroll
        for (int j = 0; j < 8; j++) acc[i][j] = 0.0f;

    const float4* yT4 = (const float4*)yT;
    const float4* RT4 = (const float4*)RT;
    #pragma unroll 8
    for (int k = 0; k < 128; k++) {
        float4 a  = yT4[k * 17 + tr];
        float4 b0 = RT4[k * 33 + tc * 2];
        float4 b1 = RT4[k * 33 + tc * 2 + 1];
        float av[4] = {a.x, a.y, a.z, a.w};
        float bv[8] = {b0.x, b0.y, b0.z, b0.w, b1.x, b1.y, b1.z, b1.w};
        #pragma unroll
        for (int i = 0; i < 4; i++)
            #pragma unroll
            for (int j = 0; j < 8; j++) acc[i][j] += av[i] * bv[j];
    }
    float tv[8];
    #pragma unroll
    for (int j = 0; j < 8; j++) tv[j] = t[tc * 8 + j];
    #pragma unroll
    for (int i = 0; i < 4; i++) {
        int row = r0 + tr * 4 + i;
        #pragma unroll
        for (int j = 0; j < 8; j++) {
            int c = tc * 8 + j;
            g_ytb[row * 128 + (c & ~15) + p16(c & 15)] =
                __float2bfloat16_rn(acc[i][j] + tv[j]);
        }
    }
}

// ---------------- kernel 2: scaled norms of the bf16-rounded vectors -------
__global__ __launch_bounds__(128) void norm_kernel(const float* __restrict__ X)
{
    const int row = blockIdx.x, which = blockIdx.y;
    float v = which ? __bfloat162float(g_ytb[row * 128 + threadIdx.x])
                    : __bfloat162float(__float2bfloat16_rn(X[row * 128 + threadIdx.x]));
    float s = v * v;
    #pragma unroll
    for (int o = 16; o; o >>= 1) s += __shfl_down_sync(0xFFFFFFFFu, s, o);
    __shared__ float red[4];
    if ((threadIdx.x & 31) == 0) red[threadIdx.x >> 5] = s;
    __syncthreads();
    if (threadIdx.x == 0) {
        float tot = -(red[0] + red[1] + red[2] + red[3]) * NGL2;
        if (which) g_ck[row] = (row < NROWS) ? tot : -1e30f;
        else       g_cq[row] = tot;
    }
}

// ---------------- kernel 3: V transpose [dim][key], keys sperm-permuted ----
__global__ __launch_bounds__(256) void vt_kernel(const float* __restrict__ X)
{
    __shared__ float ts[64 * 133];
    const int tid = threadIdx.x;
    const int j0 = blockIdx.x * 64;

    #pragma unroll
    for (int i = 0; i < 8; i++) {
        int f = tid + i * 256;
        int r = f >> 5, c4 = f & 31;
        int src = j0 + r + 1; if (src > 8191) src = 8191;  // clamp; weight is 0
        float4 v = ((const float4*)X)[(size_t)src * 32 + c4];
        float* d = &ts[r * 133 + c4 * 4];
        d[0] = v.x; d[1] = v.y; d[2] = v.z; d[3] = v.w;
    }
    __syncthreads();

    const int w = tid >> 5, l = tid & 31;
    #pragma unroll
    for (int db = 0; db < 16; db++) {
        int d = db * 8 + w;
        #pragma unroll
        for (int it = 0; it < 2; it++) {
            int r = it * 32 + l;
            int jst = (r & ~7) | sperm(r & 7);
            g_vt[(size_t)d * 8192 + j0 + jst] = tf32r(ts[r * 133 + d]);
        }
    }
}

// ---------------- kernel 4: flash RBF attention --------------------------
// grid 128, 512 threads: wm=w>>2 (m16 strip), sub=w&3; GEMM1 quarter q=sub (bf16 k16);
// GEMM2 (tf32 k8): half=sub&1 (64 dims), kv=sub>>1 (32 keys). Pair (wm,kv) closes P.
// Q/K: bf16 rows of 288B (stride 32 mod 128 -> conflict-free LDS.64 of p16 quads)
// V/P: fp32 rows of 72 floats (8 mod 32 -> conflict-free LDS.64 of sperm pairs)
// 3-deep K/V/ck buffers, distance-2 cp.async prefetch.
#define QB      0
#define KBO(b)  (18432 + (b) * 18432)
#define VBO(b)  (73728 + (b) * 36864)
#define PSB     184320
#define CKB(b)  (202752 + (b) * 256)
#define DNB     203520
#define SMEM_BYTES 204544
#define SVD 72

__global__ __launch_bounds__(512, 1) void attn_kernel(const float* __restrict__ X,
                                                      float* __restrict__ out)
{
    extern __shared__ char smc[];
    const int tid = threadIdx.x;
    const int w = tid >> 5, l = tid & 31;
    const int gid = l >> 2, tig = l & 3;
    const int wm = w >> 2, sub = w & 3;
    const int half = sub & 1, kv = sub >> 1, q = sub;
    const int mb = wm * 16;
    const int r0 = blockIdx.x * 64;
    const int s0 = ((tig & 1) << 2) | (tig >> 1);   // sperm(2*tig)

    // ---- stage Q as bf16 (p16-permuted) ----
    {
        const float2* X2 = (const float2*)X;
        #pragma unroll
        for (int i = 0; i < 8; i++) {
            int f = tid + i * 512;                 // 0..4095
            int r = f >> 6, cp = f & 63, k = 2 * cp;
            float2 qv = X2[(size_t)(r0 + r) * 64 + cp];
            *(__nv_bfloat162*)(smc + QB + r * 288 + (k >> 4) * 32 + p16(k & 15) * 2) =
                __floats2bfloat162_rn(qv.x, qv.y);
        }
    }
    const float cq0 = g_cq[r0 + mb + gid];
    const float cq1 = g_cq[r0 + mb + gid + 8];

    // ---- prime tiles 0,1 -> bufs 0,1 ----
    #pragma unroll
    for (int pt = 0; pt < 2; pt++) {
        const int j0 = pt * 64;
        #pragma unroll
        for (int i = 0; i < 2; i++) {              // K: 64 rows x 16 chunks
            int f = tid + i * 512, r = f >> 4, c = f & 15;
            CP16(smaddr(smc + KBO(pt) + r * 288 + c * 16), g_ytb + (size_t)(j0 + r) * 128 + c * 8);
        }
        #pragma unroll
        for (int i = 0; i < 4; i++) {              // V: 128 rows x 16 chunks
            int f = tid + i * 512, d = f >> 4, c = f & 15;
            CP16(smaddr(smc + VBO(pt) + d * 288 + c * 16), g_vt + (size_t)d * 8192 + j0 + c * 4);
        }
        if (tid < 16) CP16(smaddr(smc + CKB(pt) + tid * 16), g_ck + j0 + tid * 4);
        CP_COMMIT();
    }
    __syncthreads();                               // Q staged

    float oa[8][4];
    #pragma unroll
    for (int n = 0; n < 8; n++)
        #pragma unroll
        for (int j = 0; j < 4; j++) oa[n][j] = 0.0f;
    float dn0 = 0.0f, dn1 = 0.0f;

    #pragma unroll 1
    for (int t = 0; t < 128; t++) {
        const int b = t % 3;

        if (t + 2 < 128) {                         // prefetch t+2 into buf (t+2)%3
            const int nb = (t + 2) % 3;
            const int j0 = (t + 2) * 64;
            #pragma unroll
            for (int i = 0; i < 2; i++) {
                int f = tid + i * 512, r = f >> 4, c = f & 15;
                CP16(smaddr(smc + KBO(nb) + r * 288 + c * 16),
                     g_ytb + (size_t)(j0 + r) * 128 + c * 8);
            }
            #pragma unroll
            for (int i = 0; i < 4; i++) {
                int f = tid + i * 512, d = f >> 4, c = f & 15;
                CP16(smaddr(smc + VBO(nb) + d * 288 + c * 16),
                     g_vt + (size_t)d * 8192 + j0 + c * 4);
            }
            if (tid < 16) CP16(smaddr(smc + CKB(nb) + tid * 16), g_ck + j0 + tid * 4);
        }
        CP_COMMIT();
        CP_WAIT2();                                // own chunks of tile t done
        __syncthreads();                           // everyone's chunks visible

        // ---- GEMM1 (bf16 k16): S[m16][16 keys q*16..] = Q @ K^T ----
        float sa[2][4];
        #pragma unroll
        for (int n = 0; n < 2; n++)
            #pragma unroll
            for (int j = 0; j < 4; j++) sa[n][j] = 0.0f;

        const char* Qp = smc + QB;
        const char* Kp = smc + KBO(b);
        #pragma unroll
        for (int kb = 0; kb < 8; kb++) {
            uint2 aA = *(const uint2*)(Qp + (mb + gid)     * 288 + kb * 32 + tig * 8); // a0,a2
            uint2 aB = *(const uint2*)(Qp + (mb + gid + 8) * 288 + kb * 32 + tig * 8); // a1,a3
            #pragma unroll
            for (int n0 = 0; n0 < 2; n0++) {
                uint2 bb = *(const uint2*)(Kp + (q * 16 + n0 * 8 + gid) * 288 + kb * 32 + tig * 8);
                mma16(sa[n0], aA.x, aB.x, aA.y, aB.y, bb.x, bb.y);
            }
        }

        // ---- P = 2^(C2*S + cq + ck); den accum; store P (sperm slots) ----
        const float* ckb = (const float*)(smc + CKB(b));
        float* Ps = (float*)(smc + PSB);
        #pragma unroll
        for (int n0 = 0; n0 < 2; n0++) {
            int cl = q * 16 + n0 * 8;
            float ck0 = ckb[cl + 2 * tig], ck1 = ckb[cl + 2 * tig + 1];
            float p0 = tf32r(ex2f(fmaf(C2, sa[n0][0], cq0 + ck0)));
            float p1 = tf32r(ex2f(fmaf(C2, sa[n0][1], cq0 + ck1)));
            float p2 = tf32r(ex2f(fmaf(C2, sa[n0][2], cq1 + ck0)));
            float p3 = tf32r(ex2f(fmaf(C2, sa[n0][3], cq1 + ck1)));
            dn0 += p0 + p1;
            dn1 += p2 + p3;
            int rA = mb + gid, rB = rA + 8;
            Ps[rA * SVD + cl + s0]     = p0;
            Ps[rA * SVD + cl + s0 + 2] = p1;
            Ps[rB * SVD + cl + s0]     = p2;
            Ps[rB * SVD + cl + s0 + 2] = p3;
        }
        // sync the 2-warp pair (wm,kv): producers of quarters 2kv,2kv+1
        asm volatile("bar.sync %0, %1;" :: "r"(1 + wm * 2 + kv), "r"(64) : "memory");

        // ---- GEMM2 (tf32 k8): O[m16][dims half*64..] += P @ V, keys [kv*32,+32) ----
        const uint32_t* PsU = (const uint32_t*)(smc + PSB);
        const uint32_t* VsU = (const uint32_t*)(smc + VBO(b));
        #pragma unroll
        for (int k0 = 0; k0 < 4; k0++) {
            int kc = kv * 32 + k0 * 8 + 2 * tig;
            uint2 p0 = *(const uint2*)&PsU[(mb + gid)     * SVD + kc];
            uint2 p1 = *(const uint2*)&PsU[(mb + gid + 8) * SVD + kc];
            #pragma unroll
            for (int n0 = 0; n0 < 8; n0++) {
                uint2 vb = *(const uint2*)&VsU[(half * 64 + n0 * 8 + gid) * SVD + kc];
                mma8(oa[n0], p0.x, p1.x, p0.y, p1.y, vb.x, vb.y);
            }
        }
        __syncthreads();                           // all reads of tile t done
    }

    // ---- epilogue: den quarters -> smem; kv=1 warps park partial O ----
    dn0 += __shfl_xor_sync(0xFFFFFFFFu, dn0, 1);
    dn0 += __shfl_xor_sync(0xFFFFFFFFu, dn0, 2);
    dn1 += __shfl_xor_sync(0xFFFFFFFFu, dn1, 1);
    dn1 += __shfl_xor_sync(0xFFFFFFFFu, dn1, 2);
    float* dnp = (float*)(smc + DNB);
    if (tig == 0) {
        dnp[q * 64 + mb + gid]     = dn0;
        dnp[q * 64 + mb + gid + 8] = dn1;
    }
    if (kv) {                                      // park partial O in retired V buf 0
        float* ob = (float*)(smc + VBO(0));
        int rA = mb + gid, rB = rA + 8;
        #pragma unroll
        for (int n0 = 0; n0 < 8; n0++) {
            int col = half * 64 + n0 * 8 + 2 * tig;
            *(float2*)&ob[rA * 132 + col] = make_float2(oa[n0][0], oa[n0][1]);
            *(float2*)&ob[rB * 132 + col] = make_float2(oa[n0][2], oa[n0][3]);
        }
    }
    __syncthreads();

    if (!kv) {                                     // reduce + normalize + write
        const float* ob = (const float*)(smc + VBO(0));
        int rA = mb + gid, rB = rA + 8;
        float dA = dnp[rA] + dnp[64 + rA] + dnp[128 + rA] + dnp[192 + rA];
        float dB = dnp[rB] + dnp[64 + rB] + dnp[128 + rB] + dnp[192 + rB];
        float iA = 1.0f / dA, iB = 1.0f / dB;
        int gA = r0 + rA, gB = r0 + rB;
        #pragma unroll
        for (int n0 = 0; n0 < 8; n0++) {
            int col = half * 64 + n0 * 8 + 2 * tig;
            float2 uA = *(const float2*)&ob[rA * 132 + col];
            float2 uB = *(const float2*)&ob[rB * 132 + col];
            if (gA < NROWS)
                *(float2*)&out[(size_t)gA * 128 + col] =
                    make_float2((oa[n0][0] + uA.x) * iA, (oa[n0][1] + uA.y) * iA);
            if (gB < NROWS)
                *(float2*)&out[(size_t)gB * 128 + col] =
                    make_float2((oa[n0][2] + uB.x) * iB, (oa[n0][3] + uB.y) * iB);
        }
    }
}

// ---------------- launch ----------------------------------------------------
extern "C" void kernel_launch(void* const* d_in, const int* in_sizes, int n_in,
                              void* d_out, int out_size)
{
    const float* X = (const float*)d_in[0];   // (8192,128)
    const float* y = (const float*)d_in[1];   // (8191,128)
    const float* R = (const float*)d_in[3];   // (128,128)
    const float* t = (const float*)d_in[4];   // (128,1)
    float* out = (float*)d_out;               // (8191,128)

    cudaFuncSetAttribute(yt_kernel,   cudaFuncAttributeMaxDynamicSharedMemorySize, 102400);
    cudaFuncSetAttribute(attn_kernel, cudaFuncAttributeMaxDynamicSharedMemorySize, SMEM_BYTES);

    yt_kernel<<<128, 256, 102400>>>(y, R, t);
    norm_kernel<<<dim3(8192, 2), 128>>>(X);
    vt_kernel<<<128, 256>>>(X);
    attn_kernel<<<128, 512, SMEM_BYTES>>>(X, out);
}

// round 14
// speedup vs baseline: 1.2107x; 1.2107x over previous
#include <cuda_runtime.h>
#include <cstdint>

#define NROWS 8191
#define C2    0.011271055006945017f    /* 2*gamma*log2(e), gamma=1/256 */
#define NGL2  0.0056355275034725085f   /* gamma*log2(e) */

// ---------------- device scratch (no allocation allowed) ----------------
__device__ float g_yt[8192 * 128];   // tf32 yt keys, dims permuted within 8
__device__ float g_vt[128 * 8192];   // tf32 V transposed [dim][key], keys permuted within 8
__device__ float g_cq[8192];         // -gamma*log2e*||x_i||^2
__device__ float g_ck[8192];         // -gamma*log2e*||yt_j||^2 ; row 8191 -> -1e30

__device__ __host__ __forceinline__ int sperm(int k) { return ((k & 3) << 1) | (k >> 2); }

__device__ __forceinline__ float tf32r(float x) {
    uint32_t u; asm("cvt.rna.tf32.f32 %0, %1;" : "=r"(u) : "f"(x));
    return __uint_as_float(u);
}
__device__ __forceinline__ float ex2f(float x) {
    float r; asm("ex2.approx.f32 %0, %1;" : "=f"(r) : "f"(x)); return r;
}
__device__ __forceinline__ uint32_t smaddr(const void* p) {
    uint32_t a;
    asm("{ .reg .u64 t; cvta.to.shared.u64 t, %1; cvt.u32.u64 %0, t; }" : "=r"(a) : "l"(p));
    return a;
}
#define CP16(dst, src) \
    asm volatile("cp.async.cg.shared.global [%0], [%1], 16;" \
                 :: "r"(dst), "l"((size_t)__cvta_generic_to_global(src)) : "memory")
#define CP_COMMIT() asm volatile("cp.async.commit_group;" ::: "memory")
#define CP_WAIT0()  asm volatile("cp.async.wait_group 0;" ::: "memory")

__device__ __forceinline__ void mma8(float* c, uint32_t a0, uint32_t a1, uint32_t a2,
                                     uint32_t a3, uint32_t b0, uint32_t b1) {
    asm volatile("mma.sync.aligned.m16n8k8.row.col.f32.tf32.tf32.f32 "
                 "{%0,%1,%2,%3}, {%4,%5,%6,%7}, {%8,%9}, {%0,%1,%2,%3};"
                 : "+f"(c[0]), "+f"(c[1]), "+f"(c[2]), "+f"(c[3])
                 : "r"(a0), "r"(a1), "r"(a2), "r"(a3), "r"(b0), "r"(b1));
}

// ---------------- kernel 1: yt = y @ R^T + t (tf32, dims permuted) ---------
__global__ __launch_bounds__(256) void yt_kernel(const float* __restrict__ y,
                                                 const float* __restrict__ R,
                                                 const float* __restrict__ t)
{
    extern __shared__ char smem[];
    float* yT = (float*)smem;
    float* RT = (float*)(smem + 34816);
    const int tid = threadIdx.x;
    const int r0  = blockIdx.x * 64;

    #pragma unroll
    for (int s = 0; s < 32; s++) {
        int e = tid + s * 256, row = e >> 7, k = e & 127, gr = r0 + row;
        yT[k * 68 + row] = (gr < NROWS) ? y[gr * 128 + k] : 0.0f;
    }
    #pragma unroll
    for (int s = 0; s < 64; s++) {
        int e = tid + s * 256, c = e >> 7, k = e & 127;
        RT[k * 132 + c] = R[e];
    }
    __syncthreads();

    const int tr = tid >> 4, tc = tid & 15;
    float acc[4][8];
    #pragma unroll
    for (int i = 0; i < 4; i++)
        #pragma unroll
        for (int j = 0; j < 8; j++) acc[i][j] = 0.0f;

    const float4* yT4 = (const float4*)yT;
    const float4* RT4 = (const float4*)RT;
    #pragma unroll 8
    for (int k = 0; k < 128; k++) {
        float4 a  = yT4[k * 17 + tr];
        float4 b0 = RT4[k * 33 + tc * 2];
        float4 b1 = RT4[k * 33 + tc * 2 + 1];
        float av[4] = {a.x, a.y, a.z, a.w};
        float bv[8] = {b0.x, b0.y, b0.z, b0.w, b1.x, b1.y, b1.z, b1.w};
        #pragma unroll
        for (int i = 0; i < 4; i++)
            #pragma unroll
            for (int j = 0; j < 8; j++) acc[i][j] += av[i] * bv[j];
    }
    float tv[8];
    #pragma unroll
    for (int j = 0; j < 8; j++) tv[j] = t[tc * 8 + j];
    #pragma unroll
    for (int i = 0; i < 4; i++) {
        int row = r0 + tr * 4 + i;
        #pragma unroll
        for (int j = 0; j < 8; j++)
            g_yt[row * 128 + tc * 8 + sperm(j)] = tf32r(acc[i][j] + tv[j]);
    }
}

// ---------------- kernel 2: scaled norms ----------------
__global__ __launch_bounds__(128) void norm_kernel(const float* __restrict__ X)
{
    const int row = blockIdx.x, which = blockIdx.y;
    float v = which ? g_yt[row * 128 + threadIdx.x]
                    : tf32r(X[row * 128 + threadIdx.x]);
    float s = v * v;
    #pragma unroll
    for (int o = 16; o; o >>= 1) s += __shfl_down_sync(0xFFFFFFFFu, s, o);
    __shared__ float red[4];
    if ((threadIdx.x & 31) == 0) red[threadIdx.x >> 5] = s;
    __syncthreads();
    if (threadIdx.x == 0) {
        float tot = -(red[0] + red[1] + red[2] + red[3]) * NGL2;
        if (which) g_ck[row] = (row < NROWS) ? tot : -1e30f;
        else       g_cq[row] = tot;
    }
}

// ---------------- kernel 3: V transpose [dim][key], keys permuted ----------
__global__ __launch_bounds__(256) void vt_kernel(const float* __restrict__ X)
{
    __shared__ float ts[64 * 133];
    const int tid = threadIdx.x;
    const int j0 = blockIdx.x * 64;

    #pragma unroll
    for (int i = 0; i < 8; i++) {
        int f = tid + i * 256;
        int r = f >> 5, c4 = f & 31;
        int src = j0 + r + 1; if (src > 8191) src = 8191;
        float4 v = ((const float4*)X)[(size_t)src * 32 + c4];
        float* d = &ts[r * 133 + c4 * 4];
        d[0] = v.x; d[1] = v.y; d[2] = v.z; d[3] = v.w;
    }
    __syncthreads();

    const int w = tid >> 5, l = tid & 31;
    #pragma unroll
    for (int db = 0; db < 16; db++) {
        int d = db * 8 + w;
        #pragma unroll
        for (int it = 0; it < 2; it++) {
            int r = it * 32 + l;
            int jst = (r & ~7) | sperm(r & 7);
            g_vt[(size_t)d * 8192 + j0 + jst] = tf32r(ts[r * 133 + d]);
        }
    }
}

// ---------------- kernel 4: flash RBF attention, overlap-restructured ------
#define SQ 136
#define SVD 72
#define QSO 0
#define KSO(b)  (8704 + (b) * 8704)
#define VSO(b)  (26112 + (b) * 9216)
#define PSO(pb) (44544 + (pb) * 4608)
#define CKO(b)  (53760 + (b) * 64)
#define DNO 53888
#define SMEM_BYTES (54144 * 4)

__global__ __launch_bounds__(512, 1) void attn_kernel(const float* __restrict__ X,
                                                      float* __restrict__ out)
{
    extern __shared__ float sm[];
    const int tid = threadIdx.x;
    const int w = tid >> 5, l = tid & 31;
    const int gid = l >> 2, tig = l & 3;
    const int wm = w >> 2, q = w & 3;
    const int hm = wm >> 1, kv = q >> 1, nq = ((wm & 1) << 1) | (q & 1);
    const int mb = wm * 16;
    const int mb2 = hm * 32;
    const int nb2 = nq * 32;
    const int barid = 1 + hm * 2 + kv;
    const int r0 = blockIdx.x * 64;
    const int s0 = ((tig & 1) << 2) | (tig >> 1);

    {
        const float4* X4 = (const float4*)X;
        #pragma unroll
        for (int i = 0; i < 4; i++) {
            int f = tid + i * 512, r = f >> 5, c4 = f & 31;
            float4 qv = X4[(size_t)(r0 + r) * 32 + c4];
            int base = QSO + r * SQ + (c4 >> 1) * 8 + (c4 & 1);
            sm[base + 0] = tf32r(qv.x); sm[base + 2] = tf32r(qv.y);
            sm[base + 4] = tf32r(qv.z); sm[base + 6] = tf32r(qv.w);
        }
    }
    const float cq0 = g_cq[r0 + mb + gid];
    const float cq1 = g_cq[r0 + mb + gid + 8];

    #pragma unroll
    for (int i = 0; i < 4; i++) {
        int f = tid + i * 512, r = f >> 5, c4 = f & 31;
        CP16(smaddr(&sm[KSO(0) + r * SQ + c4 * 4]), g_yt + r * 128 + c4 * 4);
    }
    #pragma unroll
    for (int i = 0; i < 4; i++) {
        int f = tid + i * 512, d = f >> 4, c = f & 15;
        CP16(smaddr(&sm[VSO(0) + d * SVD + c * 4]), g_vt + (size_t)d * 8192 + c * 4);
    }
    if (tid < 16) CP16(smaddr(&sm[CKO(0) + tid * 4]), g_ck + tid * 4);
    CP_COMMIT();

    float oa[2][4][4];
    #pragma unroll
    for (int m = 0; m < 2; m++)
        #pragma unroll
        for (int n = 0; n < 4; n++)
            #pragma unroll
            for (int j = 0; j < 4; j++) oa[m][n][j] = 0.0f;
    float dn0 = 0.0f, dn1 = 0.0f;

    const int qA0 = (mb + gid) * SQ + 2 * tig;
    const int qA1 = (mb + gid + 8) * SQ + 2 * tig;
    const int kB0 = (q * 16 + gid) * SQ + 2 * tig;
    const int pA0 = (mb2 + gid) * SVD;
    const int vB0 = (nb2 + gid) * SVD;

    #pragma unroll 1
    for (int t = 0; t < 128; t++) {
        const int b = t & 1;

        CP_WAIT0();
        __syncthreads();

        if (t + 1 < 128) {
            const int nb = b ^ 1;
            const int j0 = (t + 1) * 64;
            #pragma unroll
            for (int i = 0; i < 4; i++) {
                int f = tid + i * 512, r = f >> 5, c4 = f & 31;
                CP16(smaddr(&sm[KSO(nb) + r * SQ + c4 * 4]),
                     g_yt + (size_t)(j0 + r) * 128 + c4 * 4);
            }
            #pragma unroll
            for (int i = 0; i < 4; i++) {
                int f = tid + i * 512, d = f >> 4, c = f & 15;
                CP16(smaddr(&sm[VSO(nb) + d * SVD + c * 4]),
                     g_vt + (size_t)d * 8192 + j0 + c * 4);
            }
            if (tid < 16) CP16(smaddr(&sm[CKO(nb) + tid * 4]), g_ck + j0 + tid * 4);
            CP_COMMIT();
        }

        float sa[2][4];
        #pragma unroll
        for (int n = 0; n < 2; n++)
            #pragma unroll
            for (int j = 0; j < 4; j++) sa[n][j] = 0.0f;

        const uint32_t* QsU = (const uint32_t*)&sm[QSO];
        const uint32_t* KsU = (const uint32_t*)&sm[KSO(b)];
        #pragma unroll
        for (int k0 = 0; k0 < 16; k0++) {
            uint2 aA = *(const uint2*)&QsU[qA0 + k0 * 8];
            uint2 aB = *(const uint2*)&QsU[qA1 + k0 * 8];
            #pragma unroll
            for (int n0 = 0; n0 < 2; n0++) {
                uint2 bb = *(const uint2*)&KsU[kB0 + n0 * 8 * SQ + k0 * 8];
                mma8(sa[n0], aA.x, aB.x, aA.y, aB.y, bb.x, bb.y);
            }
        }

        const float* ckb = &sm[CKO(b)];
        float* Ps = &sm[PSO(b)];
        #pragma unroll
        for (int n0 = 0; n0 < 2; n0++) {
            int cl = q * 16 + n0 * 8;
            float ck0 = ckb[cl + 2 * tig], ck1 = ckb[cl + 2 * tig + 1];
            float p0 = tf32r(ex2f(fmaf(C2, sa[n0][0], cq0 + ck0)));
            float p1 = tf32r(ex2f(fmaf(C2, sa[n0][1], cq0 + ck1)));
            float p2 = tf32r(ex2f(fmaf(C2, sa[n0][2], cq1 + ck0)));
            float p3 = tf32r(ex2f(fmaf(C2, sa[n0][3], cq1 + ck1)));
            dn0 += p0 + p1;
            dn1 += p2 + p3;
            int rA = mb + gid, rB = rA + 8;
            Ps[rA * SVD + cl + s0]     = p0;
            Ps[rA * SVD + cl + s0 + 2] = p1;
            Ps[rB * SVD + cl + s0]     = p2;
            Ps[rB * SVD + cl + s0 + 2] = p3;
        }
        asm volatile("bar.sync %0, %1;" :: "r"(barid), "r"(128) : "memory");

        const uint32_t* PsU = (const uint32_t*)&sm[PSO(b)];
        const uint32_t* VsU = (const uint32_t*)&sm[VSO(b)];
        #pragma unroll
        for (int k0 = 0; k0 < 4; k0++) {
            int kc = kv * 32 + k0 * 8 + 2 * tig;
            uint2 p0 = *(const uint2*)&PsU[pA0 + kc];
            uint2 p1 = *(const uint2*)&PsU[pA0 + 8 * SVD + kc];
            uint2 p2 = *(const uint2*)&PsU[pA0 + 16 * SVD + kc];
            uint2 p3 = *(const uint2*)&PsU[pA0 + 24 * SVD + kc];
            #pragma unroll
            for (int n0 = 0; n0 < 4; n0++) {
                uint2 vb = *(const uint2*)&VsU[vB0 + n0 * 8 * SVD + kc];
                mma8(oa[0][n0], p0.x, p1.x, p0.y, p1.y, vb.x, vb.y);
                mma8(oa[1][n0], p2.x, p3.x, p2.y, p3.y, vb.x, vb.y);
            }
        }
    }

    dn0 += __shfl_xor_sync(0xFFFFFFFFu, dn0, 1);
    dn0 += __shfl_xor_sync(0xFFFFFFFFu, dn0, 2);
    dn1 += __shfl_xor_sync(0xFFFFFFFFu, dn1, 1);
    dn1 += __shfl_xor_sync(0xFFFFFFFFu, dn1, 2);
    if (tig == 0) {
        sm[DNO + q * 64 + mb + gid]     = dn0;
        sm[DNO + q * 64 + mb + gid + 8] = dn1;
    }
    if (kv) {
        float* ob = &sm[VSO(0)];
        #pragma unroll
        for (int m = 0; m < 2; m++) {
            int rA = mb2 + gid + 16 * m, rB = rA + 8;
            #pragma unroll
            for (int n0 = 0; n0 < 4; n0++) {
                int col = nb2 + n0 * 8 + 2 * tig;
                *(float2*)&ob[rA * 132 + col] = make_float2(oa[m][n0][0], oa[m][n0][1]);
                *(float2*)&ob[rB * 132 + col] = make_float2(oa[m][n0][2], oa[m][n0][3]);
            }
        }
    }
    __syncthreads();

    if (!kv) {
        const float* ob = &sm[VSO(0)];
        #pragma unroll
        for (int m = 0; m < 2; m++) {
            int rA = mb2 + gid + 16 * m, rB = rA + 8;
            float dA = sm[DNO + rA] + sm[DNO + 64 + rA] + sm[DNO + 128 + rA] + sm[DNO + 192 + rA];
            float dB = sm[DNO + rB] + sm[DNO + 64 + rB] + sm[DNO + 128 + rB] + sm[DNO + 192 + rB];
            float iA = 1.0f / dA, iB = 1.0f / dB;
            int gA = r0 + rA, gB = r0 + rB;
            #pragma unroll
            for (int n0 = 0; n0 < 4; n0++) {
                int col = nb2 + n0 * 8 + 2 * tig;
                float2 uA = *(const float2*)&ob[rA * 132 + col];
                float2 uB = *(const float2*)&ob[rB * 132 + col];
                if (gA < NROWS)
                    *(float2*)&out[(size_t)gA * 128 + col] =
                        make_float2((oa[m][n0][0] + uA.x) * iA, (oa[m][n0][1] + uA.y) * iA);
                if (gB < NROWS)
                    *(float2*)&out[(size_t)gB * 128 + col] =
                        make_float2((oa[m][n0][2] + uB.x) * iB, (oa[m][n0][3] + uB.y) * iB);
            }
        }
    }
}

// ---------------- launch ----------------------------------------------------
extern "C" void kernel_launch(void* const* d_in, const int* in_sizes, int n_in,
                              void* d_out, int out_size)
{
    const float* X = (const float*)d_in[0];
    const float* y = (const float*)d_in[1];
    const float* R = (const float*)d_in[3];
    const float* t = (const float*)d_in[4];
    float* out = (float*)d_out;

    cudaFuncSetAttribute(yt_kernel,   cudaFuncAttributeMaxDynamicSharedMemorySize, 102400);
    cudaFuncSetAttribute(attn_kernel, cudaFuncAttributeMaxDynamicSharedMemorySize, SMEM_BYTES);

    yt_kernel<<<128, 256, 102400>>>(y, R, t);
    norm_kernel<<<dim3(8192, 2), 128>>>(X);
    vt_kernel<<<128, 256>>>(X);
    attn_kernel<<<128, 512, SMEM_BYTES>>>(X, out);
}